// round 15
// baseline (speedup 1.0000x reference)
#include <cuda_runtime.h>
#include <cuda_bf16.h>
#include <cuda_fp16.h>
#include <cstdint>

// ---------------------------------------------------------------------------
// Problem constants (fixed by the reference setup)
// ---------------------------------------------------------------------------
#define BS    2
#define QTOT  21760        // = V = sum of level areas
#define CEMB  256
#define HEADS 8
#define DH    32           // C / HEADS
#define LVLS  4
#define PTS   4
#define MTOT  (BS * QTOT)  // 43520 rows for all GEMMs

__device__ __constant__ int c_lvl_wh[LVLS]    = {128, 64, 32, 16};
__device__ __constant__ int c_lvl_start[LVLS] = {0, 16384, 20480, 21504};

// ---------------------------------------------------------------------------
// Scratch (static device globals; no runtime allocation)
// ---------------------------------------------------------------------------
__device__ __align__(16) __half g_valh[(size_t)BS * QTOT * CEMB];  // [b][h][v][d] fp16
__device__ __align__(16) float g_off [(size_t)BS * QTOT * CEMB];   // [b][q][256]
__device__ __align__(16) float g_attn[(size_t)BS * QTOT * 128];    // [b][q][128]

// bf16 hi/lo split activations: 3 segments (value, query, mid), [M][256] each
#define SEGSZ ((size_t)MTOT * 256)
__device__ __align__(16) __nv_bfloat16 g_ahi[3 * SEGSZ];
__device__ __align__(16) __nv_bfloat16 g_alo[3 * SEGSZ];

// transposed + split weights: [N][K=256] bf16, hi and lo parts
// NOTE: W_off rows [256) and W_attn rows [256,384) are contiguous -> fused GEMM
#define WT_TOTAL 229376
__device__ __align__(16) __nv_bfloat16 g_bt_hi[WT_TOTAL];
__device__ __align__(16) __nv_bfloat16 g_bt_lo[WT_TOTAL];
#define OFF_WV    0
#define OFF_WOFF  65536
#define OFF_WATTN 131072
#define OFF_WOUT  163840

// ---------------------------------------------------------------------------
// sm_80-era PTX helpers (all legal for plain sm_103 target)
// ---------------------------------------------------------------------------
__device__ __forceinline__ uint32_t smem_u32(const void* p) {
    uint32_t a;
    asm("{ .reg .u64 t; cvta.to.shared.u64 t, %1; cvt.u32.u64 %0, t; }"
        : "=r"(a) : "l"(p));
    return a;
}
__device__ __forceinline__ void cpa16(uint32_t dst, const void* src) {
    asm volatile("cp.async.cg.shared.global [%0], [%1], 16;" :: "r"(dst), "l"(src));
}
#define CP_COMMIT() asm volatile("cp.async.commit_group;" ::: "memory")
#define CP_WAIT1()  asm volatile("cp.async.wait_group 1;"  ::: "memory")

__device__ __forceinline__ void ldsm4(uint32_t* r, uint32_t a) {
    asm volatile("ldmatrix.sync.aligned.m8n8.x4.shared.b16 {%0,%1,%2,%3}, [%4];"
                 : "=r"(r[0]), "=r"(r[1]), "=r"(r[2]), "=r"(r[3]) : "r"(a));
}
__device__ __forceinline__ void mma16816(float* c, const uint32_t* a,
                                         uint32_t b0, uint32_t b1) {
    asm volatile(
        "mma.sync.aligned.m16n8k16.row.col.f32.bf16.bf16.f32 "
        "{%0,%1,%2,%3}, {%4,%5,%6,%7}, {%8,%9}, {%0,%1,%2,%3};"
        : "+f"(c[0]), "+f"(c[1]), "+f"(c[2]), "+f"(c[3])
        : "r"(a[0]), "r"(a[1]), "r"(a[2]), "r"(a[3]), "r"(b0), "r"(b1));
}

// ---------------------------------------------------------------------------
// Weight convert: W[K=256][N] fp32 -> transposed [N][256] bf16 hi/lo
// ---------------------------------------------------------------------------
__global__ void convert_w_kernel(const float* __restrict__ w0, const float* __restrict__ w1,
                                 const float* __restrict__ w2, const float* __restrict__ w3)
{
    const int id = blockIdx.y;
    const float* src = (id == 0) ? w0 : (id == 1) ? w1 : (id == 2) ? w2 : w3;
    const int N    = (id == 2) ? 128 : 256;
    const int off  = (id == 0) ? OFF_WV : (id == 1) ? OFF_WOFF
                   : (id == 2) ? OFF_WATTN : OFF_WOUT;
    const int tot  = 256 * N;
    int i = blockIdx.x * blockDim.x + threadIdx.x;
    if (i >= tot) return;
    int k = i / N, n = i - k * N;
    float x = src[i];
    __nv_bfloat16 hi = __float2bfloat16(x);
    __nv_bfloat16 lo = __float2bfloat16(x - __bfloat162float(hi));
    g_bt_hi[off + n * 256 + k] = hi;
    g_bt_lo[off + n * 256 + k] = lo;
}

// ---------------------------------------------------------------------------
// Activation convert: [M][256] fp32 -> bf16 hi/lo (vectorized)
// ---------------------------------------------------------------------------
__global__ void convert_a_kernel(const float4* __restrict__ src,
                                 __nv_bfloat162* __restrict__ hi,
                                 __nv_bfloat162* __restrict__ lo, int n4)
{
    int i = blockIdx.x * blockDim.x + threadIdx.x;
    if (i >= n4) return;
    float4 v = src[i];
    __nv_bfloat162 h01 = __floats2bfloat162_rn(v.x, v.y);
    __nv_bfloat162 h23 = __floats2bfloat162_rn(v.z, v.w);
    __nv_bfloat162 l01 = __floats2bfloat162_rn(v.x - __low2float(h01),
                                               v.y - __high2float(h01));
    __nv_bfloat162 l23 = __floats2bfloat162_rn(v.z - __low2float(h23),
                                               v.w - __high2float(h23));
    hi[i * 2]     = h01;
    hi[i * 2 + 1] = h23;
    lo[i * 2]     = l01;
    lo[i * 2 + 1] = l23;
}

// ---------------------------------------------------------------------------
// HMMA split-bf16 GEMM.
// K' = 768 concatenation: kc 0-3: Ahi*Bhi, 4-7: Alo*Bhi, 8-11: Ahi*Blo.
// 8 warps, warp tile 32x64, 3-stage cp.async pipeline, xor-swizzled smem.
// MODE 0: C row-major [M][ldc]
// MODE 1: g_valh permuted fp16 layout
// MODE 2: fused off/attn: cols [0,256) -> g_off [M][256]; [256,384) -> g_attn [M][128]
// ---------------------------------------------------------------------------
#define KC      64
#define NCHUNK  12
#define STAGEB  32768       // A 16KB + B 16KB per stage
#define NSTAGE  3

template <int MODE>
__global__ __launch_bounds__(256, 2)
void gemm_hmma(const __nv_bfloat16* __restrict__ Ahi,
               const __nv_bfloat16* __restrict__ Alo,
               const __nv_bfloat16* __restrict__ Bhi,
               const __nv_bfloat16* __restrict__ Blo,
               const float* __restrict__ bias,
               const float* __restrict__ bias2,
               float* __restrict__ C, int ldc)
{
    extern __shared__ __align__(128) char smem[];
    const uint32_t su = smem_u32(smem);

    const int tid  = threadIdx.x;
    const int lane = tid & 31;
    const int wid  = tid >> 5;
    const int wm   = wid & 3;          // 4 warps along M (32 rows each)
    const int wn   = wid >> 2;         // 2 warps along N (64 cols each)
    const int row0    = blockIdx.y * 128;
    const int colbase = blockIdx.x * 128;

    float acc[2][8][4];
    #pragma unroll
    for (int i = 0; i < 2; i++)
        #pragma unroll
        for (int j = 0; j < 8; j++)
            #pragma unroll
            for (int k = 0; k < 4; k++) acc[i][j][k] = 0.f;

    // ---- async stage loader: 2048 16B chunks (A then B), 8 per thread
    auto issue = [&](int kc, int s) {
        if (kc < NCHUNK) {
            const __nv_bfloat16* Asrc = (kc >= 4 && kc < 8) ? Alo : Ahi;
            const __nv_bfloat16* Bsrc = (kc < 8) ? Bhi : Blo;
            const int k0 = (kc & 3) * KC;
            const uint32_t sa = su + s * STAGEB;
            const uint32_t sb = sa + 16384;
            #pragma unroll
            for (int i = 0; i < 4; i++) {
                int idx = tid + i * 256;
                int r = idx >> 3, c = idx & 7;
                uint32_t sw = (uint32_t)((c ^ (r & 7)) << 4);
                cpa16(sa + r * 128 + sw,
                      Asrc + (size_t)(row0 + r) * 256 + k0 + c * 8);
                cpa16(sb + r * 128 + sw,
                      Bsrc + (size_t)(colbase + r) * 256 + k0 + c * 8);
            }
        }
        CP_COMMIT();
    };

    issue(0, 0);
    issue(1, 1);

    for (int kc = 0; kc < NCHUNK; kc++) {
        CP_WAIT1();
        __syncthreads();                       // also protects stage reuse below
        issue(kc + 2, (kc + 2) % NSTAGE);

        const uint32_t sa = su + (kc % NSTAGE) * STAGEB;
        const uint32_t sb = sa + 16384;

        #pragma unroll
        for (int kk = 0; kk < 4; kk++) {
            uint32_t af[2][4];
            #pragma unroll
            for (int tm = 0; tm < 2; tm++) {
                int r  = wm * 32 + tm * 16 + (lane & 15);
                int ch = kk * 2 + (lane >> 4);
                ldsm4(af[tm], sa + r * 128 + ((ch ^ (r & 7)) << 4));
            }
            uint32_t bf[4][4];
            #pragma unroll
            for (int tn = 0; tn < 4; tn++) {
                int r  = wn * 64 + tn * 16 + (lane & 15);
                int ch = kk * 2 + (lane >> 4);
                ldsm4(bf[tn], sb + r * 128 + ((ch ^ (r & 7)) << 4));
            }
            #pragma unroll
            for (int tm = 0; tm < 2; tm++)
                #pragma unroll
                for (int n8 = 0; n8 < 8; n8++) {
                    int tn = n8 >> 1, half = n8 & 1;
                    mma16816(acc[tm][n8], af[tm], bf[tn][half], bf[tn][half + 2]);
                }
        }
        // no trailing sync: next iteration's barrier (after CP_WAIT1) orders
        // all reads of stage (kc)%3 before issue() overwrites it
    }

    // ---- epilogue (QTOT % 128 == 0, so a 128-row tile never crosses b)
    #pragma unroll
    for (int tm = 0; tm < 2; tm++) {
        const int gr = row0 + wm * 32 + tm * 16 + (lane >> 2);
        #pragma unroll
        for (int n8 = 0; n8 < 8; n8++) {
            const int col = colbase + wn * 64 + n8 * 8 + (lane & 3) * 2;
            float bx, by;
            if (MODE == 2 && col >= 256) {
                bx = bias2[col - 256]; by = bias2[col - 255];
            } else {
                bx = bias[col]; by = bias[col + 1];
            }
            float2 v0 = make_float2(acc[tm][n8][0] + bx, acc[tm][n8][1] + by);
            float2 v1 = make_float2(acc[tm][n8][2] + bx, acc[tm][n8][3] + by);
            if (MODE == 0) {
                *(float2*)(C + (size_t)gr * ldc + col)       = v0;
                *(float2*)(C + (size_t)(gr + 8) * ldc + col) = v1;
            } else if (MODE == 1) {
                int h = col >> 5, dc = col & 31;
                int b = gr / QTOT, q = gr - b * QTOT;
                size_t base = (((size_t)(b * HEADS + h)) * QTOT + q) * DH + dc;
                *(__half2*)(g_valh + base)          = __floats2half2_rn(v0.x, v0.y);
                *(__half2*)(g_valh + base + 8 * DH) = __floats2half2_rn(v1.x, v1.y);
            } else {
                if (col < 256) {
                    *(float2*)(g_off + (size_t)gr * 256 + col)       = v0;
                    *(float2*)(g_off + (size_t)(gr + 8) * 256 + col) = v1;
                } else {
                    *(float2*)(g_attn + (size_t)gr * 128 + col - 256)       = v0;
                    *(float2*)(g_attn + (size_t)(gr + 8) * 128 + col - 256) = v1;
                }
            }
        }
    }
}

// ---------------------------------------------------------------------------
// Sampler: one block per (b,q); taps precomputed in smem; fp16 value gathers.
// Writes mid directly as bf16 hi/lo into g_ahi/g_alo segment 2.
// ---------------------------------------------------------------------------
__global__ __launch_bounds__(256, 8)
void sample_kernel(const float* __restrict__ ref)
{
    const int bq = blockIdx.x;
    const int b  = bq / QTOT;
    const int t  = threadIdx.x;

    __shared__ float  s_w[128];
    __shared__ float2 s_tap[512];
    __shared__ float  s_ref[2 * LVLS];

    if (t < 128) s_w[t] = g_attn[(size_t)bq * 128 + t];
    if (t < 2 * LVLS) s_ref[t] = ref[(size_t)bq * (2 * LVLS) + t];
    __syncthreads();

    if (t < HEADS) {
        float m = -1e30f;
        #pragma unroll
        for (int i = 0; i < 16; i++) m = fmaxf(m, s_w[t * 16 + i]);
        float s = 0.f;
        #pragma unroll
        for (int i = 0; i < 16; i++) {
            float e = expf(s_w[t * 16 + i] - m);
            s_w[t * 16 + i] = e;
            s += e;
        }
        float inv = 1.f / s;
        #pragma unroll
        for (int i = 0; i < 16; i++) s_w[t * 16 + i] *= inv;
    }
    __syncthreads();

    if (t < 128) {
        const int h  = t >> 4;
        const int pt = t & 15;
        const int l  = pt >> 2;
        const int p  = pt & 3;

        const float ox = g_off[(size_t)bq * 256 + h * 32 + l * 8 + p * 2 + 0];
        const float oy = g_off[(size_t)bq * 256 + h * 32 + l * 8 + p * 2 + 1];
        const float aw = s_w[h * 16 + pt];

        const int   W   = c_lvl_wh[l];
        const int   st  = c_lvl_start[l];
        const float fW  = (float)W;
        const float inv = 1.0f / fW;

        float x = (s_ref[l * 2 + 0] + ox * inv) * fW - 0.5f;
        float y = (s_ref[l * 2 + 1] + oy * inv) * fW - 0.5f;

        float x0f = floorf(x), y0f = floorf(y);
        int   x0 = (int)x0f,   y0 = (int)y0f;
        float fx = x - x0f,    fy = y - y0f;
        float gx = 1.f - fx,   gy = 1.f - fy;

        bool vx0 = (x0 >= 0)     & (x0 < W);
        bool vx1 = (x0 + 1 >= 0) & (x0 + 1 < W);
        bool vy0 = (y0 >= 0)     & (y0 < W);
        bool vy1 = (y0 + 1 >= 0) & (y0 + 1 < W);

        float w00 = (vx0 & vy0) ? gx * gy * aw : 0.f;
        float w10 = (vx1 & vy0) ? fx * gy * aw : 0.f;
        float w01 = (vx0 & vy1) ? gx * fy * aw : 0.f;
        float w11 = (vx1 & vy1) ? fx * fy * aw : 0.f;

        int i00 = (vx0 & vy0) ? st + y0 * W + x0           : st;
        int i10 = (vx1 & vy0) ? st + y0 * W + x0 + 1       : st;
        int i01 = (vx0 & vy1) ? st + (y0 + 1) * W + x0     : st;
        int i11 = (vx1 & vy1) ? st + (y0 + 1) * W + x0 + 1 : st;

        float2* tp = &s_tap[t * 4];
        tp[0] = make_float2(w00, __int_as_float(i00));
        tp[1] = make_float2(w10, __int_as_float(i10));
        tp[2] = make_float2(w01, __int_as_float(i01));
        tp[3] = make_float2(w11, __int_as_float(i11));
    }
    __syncthreads();

    const int h  = t >> 5;
    const int dc = t & 31;
    const __half* __restrict__ valb =
        g_valh + ((size_t)(b * HEADS + h)) * QTOT * DH + dc;
    const float2* __restrict__ tap = &s_tap[h * 64];

    float a0 = 0.f, a1 = 0.f, a2 = 0.f, a3 = 0.f;
    #pragma unroll 16
    for (int k = 0; k < 64; k += 4) {
        float2 t0 = tap[k + 0];
        float2 t1 = tap[k + 1];
        float2 t2 = tap[k + 2];
        float2 t3 = tap[k + 3];
        a0 = fmaf(t0.x, __half2float(valb[(size_t)__float_as_int(t0.y) * DH]), a0);
        a1 = fmaf(t1.x, __half2float(valb[(size_t)__float_as_int(t1.y) * DH]), a1);
        a2 = fmaf(t2.x, __half2float(valb[(size_t)__float_as_int(t2.y) * DH]), a2);
        a3 = fmaf(t3.x, __half2float(valb[(size_t)__float_as_int(t3.y) * DH]), a3);
    }
    float v = (a0 + a1) + (a2 + a3);
    __nv_bfloat16 hv = __float2bfloat16(v);
    __nv_bfloat16 lv = __float2bfloat16(v - __bfloat162float(hv));
    g_ahi[2 * SEGSZ + (size_t)bq * 256 + t] = hv;
    g_alo[2 * SEGSZ + (size_t)bq * 256 + t] = lv;
}

// ---------------------------------------------------------------------------
// Launch
// ---------------------------------------------------------------------------
extern "C" void kernel_launch(void* const* d_in, const int* in_sizes, int n_in,
                              void* d_out, int out_size)
{
    const float* query  = (const float*)d_in[0];
    const float* value  = (const float*)d_in[1];
    const float* refpts = (const float*)d_in[2];
    // d_in[3] = spatial_shapes (compile-time constants here)
    const float* W_off  = (const float*)d_in[4];
    const float* b_off  = (const float*)d_in[5];
    const float* W_attn = (const float*)d_in[6];
    const float* b_attn = (const float*)d_in[7];
    const float* W_v    = (const float*)d_in[8];
    const float* b_v    = (const float*)d_in[9];
    const float* W_out  = (const float*)d_in[10];
    const float* b_out  = (const float*)d_in[11];
    float* out = (float*)d_out;

    __nv_bfloat16 *p_ahi, *p_alo, *p_bh, *p_bl;
    cudaGetSymbolAddress((void**)&p_ahi,  g_ahi);
    cudaGetSymbolAddress((void**)&p_alo,  g_alo);
    cudaGetSymbolAddress((void**)&p_bh,   g_bt_hi);
    cudaGetSymbolAddress((void**)&p_bl,   g_bt_lo);

    const int SMEMSZ = NSTAGE * STAGEB;   // 98304
    cudaFuncSetAttribute(gemm_hmma<0>,
                         cudaFuncAttributeMaxDynamicSharedMemorySize, SMEMSZ);
    cudaFuncSetAttribute(gemm_hmma<1>,
                         cudaFuncAttributeMaxDynamicSharedMemorySize, SMEMSZ);
    cudaFuncSetAttribute(gemm_hmma<2>,
                         cudaFuncAttributeMaxDynamicSharedMemorySize, SMEMSZ);

    const int N4 = (int)(SEGSZ / 4);
    dim3 blk(256);
    dim3 grid2(2, MTOT / 128);                // N=256 GEMMs
    dim3 grid3(3, MTOT / 128);                // fused N=384 GEMM

    // 0) weight + activation converts
    convert_w_kernel<<<dim3(128, 4), 512>>>(W_v, W_off, W_attn, W_out);
    convert_a_kernel<<<N4 / 256, blk>>>((const float4*)value,
                                        (__nv_bfloat162*)p_ahi,
                                        (__nv_bfloat162*)p_alo, N4);
    convert_a_kernel<<<N4 / 256, blk>>>((const float4*)query,
                                        (__nv_bfloat162*)(p_ahi + SEGSZ),
                                        (__nv_bfloat162*)(p_alo + SEGSZ), N4);

    // 1) val = value @ W_v + b_v  -> g_valh (fp16, permuted layout)
    gemm_hmma<1><<<grid2, blk, SMEMSZ>>>(p_ahi, p_alo,
                                         p_bh + OFF_WV, p_bl + OFF_WV,
                                         b_v, nullptr, nullptr, 256);
    // 2+3) fused: [off | attn] = query @ [W_off | W_attn] + [b_off | b_attn]
    gemm_hmma<2><<<grid3, blk, SMEMSZ>>>(p_ahi + SEGSZ, p_alo + SEGSZ,
                                         p_bh + OFF_WOFF, p_bl + OFF_WOFF,
                                         b_off, b_attn, nullptr, 0);
    // 4) deformable sampling -> mid (bf16 hi/lo, segment 2)
    sample_kernel<<<MTOT, blk>>>(refpts);
    // 5) out = mid @ W_out + b_out
    gemm_hmma<0><<<grid2, blk, SMEMSZ>>>(p_ahi + 2 * SEGSZ, p_alo + 2 * SEGSZ,
                                         p_bh + OFF_WOUT, p_bl + OFF_WOUT,
                                         b_out, nullptr, out, 256);
}